// round 13
// baseline (speedup 1.0000x reference)
#include <cuda_runtime.h>
#include <cuda_fp16.h>
#include <stdint.h>

#define NB   4096
#define NOUTC 3

// ---- shared memory (bytes): ROOT(2x128 f32) | B0: 128 rows | B1: 64 rows ----
#define OFF_ROOT 0
#define OFF_B0   1024
#define B0_CS    16384
#define OFF_B1   (OFF_B0 + 4 * B0_CS)       // 66560
#define B1_CS    8192
#define SMEM_BYTES (OFF_B1 + 4 * B1_CS)     // 99328  (2 CTAs/SM)

__device__ int g_tok_is_i32;

__global__ void detect_tok_kernel(const unsigned int* __restrict__ w) {
    __shared__ int s;
    if (threadIdx.x == 0) s = 0;
    __syncthreads();
    int any = 0;
    for (int i = threadIdx.x; i < 2048; i += 256)
        any |= (w[2 * i + 1] != 0u);
    if (any) atomicOr(&s, 1);
    __syncthreads();
    if (threadIdx.x == 0) g_tok_is_i32 = s;
}

static __device__ __forceinline__ uint32_t sw128(uint32_t b) {
    return b ^ ((b >> 3) & 0x70);
}
static __device__ __forceinline__ uint32_t smem_u32(const void* p) {
    uint32_t a;
    asm("{ .reg .u64 t; cvta.to.shared.u64 t, %1; cvt.u32.u64 %0, t; }" : "=r"(a) : "l"(p));
    return a;
}
static __device__ __forceinline__ void ldsm4(uint32_t addr, uint32_t& r0, uint32_t& r1,
                                             uint32_t& r2, uint32_t& r3) {
    asm volatile("ldmatrix.sync.aligned.m8n8.x4.shared.b16 {%0,%1,%2,%3}, [%4];"
                 : "=r"(r0), "=r"(r1), "=r"(r2), "=r"(r3) : "r"(addr));
}
static __device__ __forceinline__ void mma_f16(float& d0, float& d1, float& d2, float& d3,
                                               const uint32_t a[4], uint32_t b0, uint32_t b1) {
    asm volatile("mma.sync.aligned.m16n8k16.row.col.f32.f16.f16.f32 "
                 "{%0,%1,%2,%3}, {%4,%5,%6,%7}, {%8,%9}, {%0,%1,%2,%3};"
                 : "+f"(d0), "+f"(d1), "+f"(d2), "+f"(d3)
                 : "r"(a[0]), "r"(a[1]), "r"(a[2]), "r"(a[3]), "r"(b0), "r"(b1));
}
static __device__ __forceinline__ float tanh_fast(float x) {
    float t = __expf(2.0f * x);
    return 1.0f - __fdividef(2.0f, t + 1.0f);
}
static __device__ __forceinline__ uint32_t pack_h2(float x, float y) {
    __half h0 = __float2half_rn(x), h1 = __float2half_rn(y);
    return ((uint32_t)*(uint16_t*)&h1 << 16) | *(uint16_t*)&h0;
}
// 4B store of packed (k, k+1) halves for row r; k even.
static __device__ __forceinline__ void store32(char* sm, uint32_t dstHi, uint32_t dcs,
                                               int r, int k, uint32_t w) {
    int chunk = k >> 6;
    uint32_t off = sw128((uint32_t)(r * 128 + (k & 63) * 2));
    *(uint32_t*)(sm + dstHi + (uint32_t)chunk * dcs + off) = w;
}

// One level over 2 trees; pipelined MMA -> prefetch -> epilogue.
// LDSM addressing hoisted: addr(j, nb) = base[j&1] + (j>>1)*scs + nb*1024.
template<int NTILES, int SPT, bool LAST>
static __device__ __forceinline__ void run_level(
    char* sm, uint32_t sb, uint32_t srcHi, uint32_t scs, uint32_t dstHi, uint32_t dcs,
    const uint32_t A[16][4],
    float bias0, float bias1, int wq, int lane, float* rootp)
{
    const int g = lane >> 3, lr = lane & 7;
    const uint32_t aE = sb + srcHi + sw128((uint32_t)(lr * 128 + g * 16));
    const uint32_t aO = sb + srcHi + sw128((uint32_t)(lr * 128 + 64 + g * 16));
    uint32_t Bh[16][2];

    // prologue: load tile 0
#pragma unroll
    for (int j = 0; j < 8; j++) {
        uint32_t addr = ((j & 1) ? aO : aE) + (uint32_t)((j >> 1) * scs);
        ldsm4(addr, Bh[2 * j][0], Bh[2 * j][1], Bh[2 * j + 1][0], Bh[2 * j + 1][1]);
    }

#pragma unroll 1
    for (int nb = 0; nb < NTILES; nb++) {
        float c00 = 0.f, c01 = 0.f, c02 = 0.f, c03 = 0.f;
        float c10 = 0.f, c11 = 0.f, c12 = 0.f, c13 = 0.f;
#pragma unroll
        for (int kt = 0; kt < 16; kt += 2) {
            mma_f16(c00, c01, c02, c03, A[kt],     Bh[kt][0],     Bh[kt][1]);
            mma_f16(c10, c11, c12, c13, A[kt + 1], Bh[kt + 1][0], Bh[kt + 1][1]);
        }

        // prefetch next tile (WAR-safe in issue order)
        if (nb + 1 < NTILES) {
            const uint32_t nbOff = (uint32_t)(nb + 1) * 1024u;
#pragma unroll
            for (int j = 0; j < 8; j++) {
                uint32_t addr = ((j & 1) ? aO : aE) + (uint32_t)((j >> 1) * scs) + nbOff;
                ldsm4(addr, Bh[2 * j][0], Bh[2 * j][1], Bh[2 * j + 1][0], Bh[2 * j + 1][1]);
            }
        }

        float d0 = bias0 + (c00 + c10);
        float d1 = bias0 + (c01 + c11);
        float d2 = bias1 + (c02 + c12);
        float d3 = bias1 + (c03 + c13);

        const int e0 = wq * 16 + (lane >> 2);
        const int nL = nb * 8 + 2 * (lane & 3);
        if constexpr (!LAST) {
            float t0 = tanh_fast(d0), t1 = tanh_fast(d1);
            float t2 = tanh_fast(d2), t3 = tanh_fast(d3);
            // lanes L and L^4 hold e-columns (e0, e0+1) for the same nodes
            float p0 = __shfl_xor_sync(0xffffffffu, t0, 4);
            float p1 = __shfl_xor_sync(0xffffffffu, t1, 4);
            float p2 = __shfl_xor_sync(0xffffffffu, t2, 4);
            float p3 = __shfl_xor_sync(0xffffffffu, t3, 4);
            if (!((lane >> 2) & 1) && nL < 2 * SPT) {     // even e-quad stores pairs
                int t0i = nL / SPT, ln0 = nL % SPT;
                int r0 = t0i * (SPT / 2) + (ln0 >> 1), k0 = (ln0 & 1) * 128;
                int n1 = nL + 1, t1i = n1 / SPT, ln1 = n1 % SPT;
                int r1 = t1i * (SPT / 2) + (ln1 >> 1), k1 = (ln1 & 1) * 128;
                store32(sm, dstHi, dcs, r0, k0 + e0,     pack_h2(t0, p0));
                store32(sm, dstHi, dcs, r1, k1 + e0,     pack_h2(t1, p1));
                store32(sm, dstHi, dcs, r0, k0 + e0 + 8, pack_h2(t2, p2));
                store32(sm, dstHi, dcs, r1, k1 + e0 + 8, pack_h2(t3, p3));
            }
        } else {
            if ((lane & 3) == 0) {
                rootp[e0]           = tanh_fast(d0);
                rootp[e0 + 8]       = tanh_fast(d2);
                rootp[128 + e0]     = tanh_fast(d1);
                rootp[128 + e0 + 8] = tanh_fast(d3);
            }
        }
    }
}

__global__ __launch_bounds__(256, 2)
void tree_kernel(const void* __restrict__ tokens_raw,
                 const float* __restrict__ emb,
                 const float* __restrict__ W_tree,
                 const float* __restrict__ b_tree,
                 const float* __restrict__ W_cls,
                 const float* __restrict__ b_cls,
                 float* __restrict__ out)
{
    extern __shared__ char sm[];
    const uint32_t sb = smem_u32(sm);
    const int tid = threadIdx.x, wq = tid >> 5, lane = tid & 31;
    const int b = blockIdx.x;                 // trees 2b, 2b+1

    // ---- leaf gather, MLP-8 batched: 1 token LDG/thread + shfl broadcast ----
    const int is32 = g_tok_is_i32;
    {
        const long long* t64 = (const long long*)tokens_raw;
        const int*       t32 = (const int*)tokens_raw;
        const int myLeaf = wq + 8 * lane;
        int myTok = is32 ? t32[b * 256 + myLeaf]
                         : (int)t64[b * 256 + myLeaf];
#pragma unroll
        for (int grp = 0; grp < 4; grp++) {
            float4 v[8];
#pragma unroll
            for (int j = 0; j < 8; j++) {
                int i = grp * 8 + j;
                int tk = __shfl_sync(0xffffffffu, myTok, i);
                v[j] = ((const float4*)emb)[(long long)tk * 32 + lane];
            }
#pragma unroll
            for (int j = 0; j < 8; j++) {
                int i = grp * 8 + j;
                int l = wq + 8 * i;
                int t = l >> 7, ll = l & 127;
                int row = t * 64 + (ll >> 1);
                int kb16 = ((ll & 1) << 7) + lane * 4;
                int chunk = kb16 >> 6, inner = kb16 & 63;
                uint32_t off = sw128((uint32_t)(row * 128 + inner * 2));
                char* dst = sm + OFF_B0 + chunk * B0_CS;
                *(uint32_t*)(dst + off)     = pack_h2(v[j].x, v[j].y);
                *(uint32_t*)(dst + off + 4) = pack_h2(v[j].z, v[j].w);
            }
        }
    }

    // ---- W fragments straight from global (m16n8k16 A-lane mapping), fp16 ----
    uint32_t A[16][4];
    {
        const int r0 = wq * 16 + (lane >> 2);
        const int c0 = (lane & 3) * 2;
#pragma unroll
        for (int kt = 0; kt < 16; kt++) {
            int k0 = kt * 16 + c0;
            float2 w00 = *(const float2*)(W_tree + r0 * 256 + k0);
            float2 w10 = *(const float2*)(W_tree + (r0 + 8) * 256 + k0);
            float2 w01 = *(const float2*)(W_tree + r0 * 256 + k0 + 8);
            float2 w11 = *(const float2*)(W_tree + (r0 + 8) * 256 + k0 + 8);
            A[kt][0] = pack_h2(w00.x, w00.y);
            A[kt][1] = pack_h2(w10.x, w10.y);
            A[kt][2] = pack_h2(w01.x, w01.y);
            A[kt][3] = pack_h2(w11.x, w11.y);
        }
    }
    const float bias0 = b_tree[wq * 16 + (lane >> 2)];
    const float bias1 = b_tree[wq * 16 + (lane >> 2) + 8];
    float* rootp = (float*)(sm + OFF_ROOT);
    __syncthreads();

    run_level<16, 64, false>(sm, sb, OFF_B0, B0_CS, OFF_B1, B1_CS, A, bias0, bias1, wq, lane, rootp);
    __syncthreads();
    run_level< 8, 32, false>(sm, sb, OFF_B1, B1_CS, OFF_B0, B0_CS, A, bias0, bias1, wq, lane, rootp);
    __syncthreads();
    run_level< 4, 16, false>(sm, sb, OFF_B0, B0_CS, OFF_B1, B1_CS, A, bias0, bias1, wq, lane, rootp);
    __syncthreads();
    run_level< 2,  8, false>(sm, sb, OFF_B1, B1_CS, OFF_B0, B0_CS, A, bias0, bias1, wq, lane, rootp);
    __syncthreads();
    run_level< 1,  4, false>(sm, sb, OFF_B0, B0_CS, OFF_B1, B1_CS, A, bias0, bias1, wq, lane, rootp);
    __syncthreads();
    run_level< 1,  2, false>(sm, sb, OFF_B1, B1_CS, OFF_B0, B0_CS, A, bias0, bias1, wq, lane, rootp);
    __syncthreads();
    run_level< 1,  1, true >(sm, sb, OFF_B0, B0_CS, OFF_B1, B1_CS, A, bias0, bias1, wq, lane, rootp);
    __syncthreads();

    // ---- classifier for both trees (6 warp-dots, fp32) ----
    if (tid < 192) {
        int w = tid >> 5;
        int t = (w >= 3) ? 1 : 0, o = w - t * 3;
        float p = 0.f;
#pragma unroll
        for (int k = 0; k < 4; k++) {
            int ee = lane + 32 * k;
            p += rootp[t * 128 + ee] * W_cls[o * 128 + ee];
        }
#pragma unroll
        for (int off = 16; off; off >>= 1)
            p += __shfl_down_sync(0xffffffffu, p, off);
        if (lane == 0) out[(2 * b + t) * NOUTC + o] = p + b_cls[o];
    }
}

extern "C" void kernel_launch(void* const* d_in, const int* in_sizes, int n_in,
                              void* d_out, int out_size)
{
    const void*  tokens = d_in[0];
    const float* emb    = (const float*)d_in[1];
    const float* W_tree = (const float*)d_in[2];
    const float* b_tree = (const float*)d_in[3];
    const float* W_cls  = (const float*)d_in[4];
    const float* b_cls  = (const float*)d_in[5];
    float* out = (float*)d_out;

    cudaFuncSetAttribute(tree_kernel,
                         cudaFuncAttributeMaxDynamicSharedMemorySize, SMEM_BYTES);

    detect_tok_kernel<<<1, 256>>>((const unsigned int*)tokens);
    tree_kernel<<<NB / 2, 256, SMEM_BYTES>>>(tokens, emb, W_tree, b_tree,
                                             W_cls, b_cls, out);
}